// round 1
// baseline (speedup 1.0000x reference)
#include <cuda_runtime.h>
#include <cuda_bf16.h>
#include <math.h>

// ---------------- geometry ----------------
#define NB     2
#define NC     8
#define NV     360
#define ND     512
#define RR     11          // taps
#define HID    176         // hidden channels
#define OC     88          // conv2 out channels = RR*NC
#define NP     (NV*ND)                 // 184320 sample columns
#define LL     (NP*RR)                 // 2027520
#define NIDX   (128*128*360)           // 5898240 indices
#define DT     128                     // d-tile
#define HW     (DT+2)                  // h columns per tile (halo)
#define HPAD   132                     // padded h row (16B multiple)

// scratch (no cudaMalloc allowed)
__device__ float g_A[2u * (unsigned)LL * 8u];      // [b][p][r][c]  ~130MB
__device__ float g_w2p[OC * HID * 4];              // padded fc2 weights

// ---------------- f32x2 helpers ----------------
__device__ __forceinline__ void ffma2(unsigned long long& c,
                                      unsigned long long a,
                                      unsigned long long b) {
    asm("fma.rn.f32x2 %0, %1, %2, %0;" : "+l"(c) : "l"(a), "l"(b));
}
__device__ __forceinline__ unsigned long long pack2(float lo, float hi) {
    unsigned long long r;
    asm("mov.b64 %0, {%1, %2};" : "=l"(r) : "f"(lo), "f"(hi));
    return r;
}
__device__ __forceinline__ float2 unpack2(unsigned long long v) {
    float2 f;
    asm("mov.b64 {%0, %1}, %2;" : "=f"(f.x), "=f"(f.y) : "l"(v));
    return f;
}

// ---------------- weight repack: fc2_w [88][176][3] -> [88][176][4] ----------------
__global__ void repack_w2(const float* __restrict__ w2) {
    int i = blockIdx.x * 256 + threadIdx.x;
    if (i >= OC * HID) return;
    float4 v;
    v.x = w2[i * 3 + 0];
    v.y = w2[i * 3 + 1];
    v.z = w2[i * 3 + 2];
    v.w = 0.f;
    ((float4*)g_w2p)[i] = v;
}

// ---------------- fused conv1+gelu+conv2, writes A[b][p][r][c] ----------------
__global__ __launch_bounds__(256, 2)
void conv_fused(const float* __restrict__ input,
                const float* __restrict__ w1,
                const float* __restrict__ b1,
                const float* __restrict__ b2) {
    extern __shared__ float smem[];
    float* x_s = smem;                 // [8][132]
    float* h_s = smem + 8 * HPAD;      // [176][132]

    const int tid  = threadIdx.x;
    const int blk  = blockIdx.x;
    const int bv   = blk >> 2;
    const int tile = blk & 3;
    const int d0   = tile * DT;
    const int b    = bv / NV;
    const int v    = bv - b * NV;

    // ---- load x halo: x_s[ci][j] = input[b,ci,v, d0-2+j], j in [0,132) ----
    for (int i = tid; i < 8 * HPAD; i += 256) {
        int ci = i / HPAD, j = i - ci * HPAD;
        int dG = d0 - 2 + j;
        float val = 0.f;
        if ((unsigned)dG < (unsigned)ND)
            val = input[(((size_t)(b * NC + ci) * NV + v) * ND) + dG];
        x_s[i] = val;
    }
    __syncthreads();

    // ---- conv1 + exact gelu -> h_s[hc][dd], dd in [0,130) <-> dG = d0-1+dd ----
    for (int idx = tid; idx < HID * HW; idx += 256) {
        int hc = idx / HW;
        int dd = idx - hc * HW;
        int dG = d0 - 1 + dd;
        float s = 0.f;
        if ((unsigned)dG < (unsigned)ND) {
            s = b1[hc];
            const float* wr = w1 + hc * 24;
#pragma unroll
            for (int ci = 0; ci < 8; ++ci) {
                const float* xr = x_s + ci * HPAD + dd; // x[dG-1..dG+1]
                s = fmaf(xr[0], wr[ci * 3 + 0], s);
                s = fmaf(xr[1], wr[ci * 3 + 1], s);
                s = fmaf(xr[2], wr[ci * 3 + 2], s);
            }
            s = 0.5f * s * (1.0f + erff(s * 0.70710678118654752f));
        }
        h_s[hc * HPAD + dd] = s;
    }
    __syncthreads();

    // ---- conv2: warp = output channel c (8 warps), lane covers 4 d positions ----
    const int c     = tid >> 5;
    const int lane  = tid & 31;
    const int dbase = lane * 4;

    unsigned long long acc[RR][2];
#pragma unroll
    for (int r = 0; r < RR; ++r) {
        float bb = b2[c * RR + r];
        acc[r][0] = pack2(bb, bb);
        acc[r][1] = pack2(bb, bb);
    }

    const float4* wbase = ((const float4*)g_w2p) + (size_t)(c * RR) * HID;

    for (int hc = 0; hc < HID; ++hc) {
        const float* hr = h_s + hc * HPAD;
        float4 h03 = *(const float4*)(hr + dbase);       // h[dd]..h[dd+3]
        float2 h45 = *(const float2*)(hr + dbase + 4);   // h[dd+4], h[dd+5]

        unsigned long long p0a = pack2(h03.x, h03.y), p0b = pack2(h03.z, h03.w); // k=0
        unsigned long long p1a = pack2(h03.y, h03.z), p1b = pack2(h03.w, h45.x); // k=1
        unsigned long long p2a = pack2(h03.z, h03.w), p2b = pack2(h45.x, h45.y); // k=2

        const float4* wp = wbase + hc;
#pragma unroll
        for (int r = 0; r < RR; ++r) {
            float4 w = __ldg(wp + (size_t)r * HID);
            unsigned long long w0 = pack2(w.x, w.x);
            unsigned long long wk1 = pack2(w.y, w.y);
            unsigned long long wk2 = pack2(w.z, w.z);
            ffma2(acc[r][0], p0a, w0);  ffma2(acc[r][1], p0b, w0);
            ffma2(acc[r][0], p1a, wk1); ffma2(acc[r][1], p1b, wk1);
            ffma2(acc[r][0], p2a, wk2); ffma2(acc[r][1], p2b, wk2);
        }
    }
    __syncthreads();   // all h_s reads done; reuse as y staging

    float* y_s = h_s;  // [128][88]
#pragma unroll
    for (int r = 0; r < RR; ++r) {
        float2 lo = unpack2(acc[r][0]);
        float2 hi = unpack2(acc[r][1]);
        int col = r * 8 + c;
        y_s[(dbase + 0) * OC + col] = lo.x;
        y_s[(dbase + 1) * OC + col] = lo.y;
        y_s[(dbase + 2) * OC + col] = hi.x;
        y_s[(dbase + 3) * OC + col] = hi.y;
    }
    __syncthreads();

    // coalesced copy: A[b][p0..p0+127][r][c], linear = (b*NP + p)*88 + (r*8+c)
    size_t gbase = ((size_t)b * NP + (size_t)v * ND + d0) * OC;
    float4* gdst = (float4*)(g_A + gbase);
    const float4* src = (const float4*)y_s;
    for (int i = tid; i < DT * OC / 4; i += 256)
        gdst[i] = src[i];
}

// ---------------- gather / interpolation ----------------
__global__ __launch_bounds__(256)
void gather_kernel(const float* __restrict__ idxs, float* __restrict__ out) {
    int j = blockIdx.x * 256 + threadIdx.x;
    if (j >= NIDX) return;

    float t  = idxs[j];
    float il = floorf(t);
    float w  = t - il;
    float w5 = w * 5.0f;
    float fw = floorf(w5);
    float lw = w5 - fw;

    int li = (int)(il * 11.0f + 5.0f + fw);
    int hi = li + 6;
    if (hi >= LL - 1) hi = LL - 2;

    float omlw = 1.0f - lw;
    float omw  = 1.0f - w;

#pragma unroll
    for (int b = 0; b < 2; ++b) {
        const float* Ab = g_A + (size_t)b * (size_t)LL * 8u;
        const float4* plo = (const float4*)(Ab + (size_t)li * 8u);
        const float4* phi = (const float4*)(Ab + (size_t)hi * 8u);
        float4 v0 = __ldg(plo + 0);   // A[li][0..3]
        float4 v1 = __ldg(plo + 1);   // A[li][4..7]
        float4 v2 = __ldg(plo + 2);   // A[li+1][0..3]
        float4 v3 = __ldg(plo + 3);   // A[li+1][4..7]
        float4 u0 = __ldg(phi + 0);
        float4 u1 = __ldg(phi + 1);
        float4 u2 = __ldg(phi + 2);
        float4 u3 = __ldg(phi + 3);

        float a0[8]  = {v0.x, v0.y, v0.z, v0.w, v1.x, v1.y, v1.z, v1.w};
        float a1[8]  = {v2.x, v2.y, v2.z, v2.w, v3.x, v3.y, v3.z, v3.w};
        float b0[8]  = {u0.x, u0.y, u0.z, u0.w, u1.x, u1.y, u1.z, u1.w};
        float b1v[8] = {u2.x, u2.y, u2.z, u2.w, u3.x, u3.y, u3.z, u3.w};

        size_t obase = (size_t)b * 8u * (size_t)NIDX + (size_t)j;
#pragma unroll
        for (int cc = 0; cc < 8; ++cc) {
            float low  = a0[cc] * omlw + a1[cc]  * lw;
            float high = b0[cc] * omlw + b1v[cc] * lw;
            out[obase + (size_t)cc * (size_t)NIDX] = low * omw + high * w;
        }
    }
}

// ---------------- launch ----------------
extern "C" void kernel_launch(void* const* d_in, const int* in_sizes, int n_in,
                              void* d_out, int out_size) {
    const float* input = (const float*)d_in[0];   // [2,8,360,512]
    const float* idxs  = (const float*)d_in[1];   // [5898240]
    const float* fc1w  = (const float*)d_in[2];   // [176,8,3]
    const float* fc1b  = (const float*)d_in[3];   // [176]
    const float* fc2w  = (const float*)d_in[4];   // [88,176,3]
    const float* fc2b  = (const float*)d_in[5];   // [88]
    float* out = (float*)d_out;

    // opt-in to >48KB dynamic smem (idempotent, capture-safe)
    static const int smem_bytes = (8 * HPAD + HID * HPAD) * sizeof(float); // 97152
    cudaFuncSetAttribute(conv_fused, cudaFuncAttributeMaxDynamicSharedMemorySize,
                         smem_bytes);

    repack_w2<<<(OC * HID + 255) / 256, 256>>>(fc2w);
    conv_fused<<<NB * NV * (ND / DT), 256, smem_bytes>>>(input, fc1w, fc1b, fc2b);
    gather_kernel<<<NIDX / 256, 256>>>(idxs, out);
}